// round 1
// baseline (speedup 1.0000x reference)
#include <cuda_runtime.h>
#include <math.h>

#define NCHUNK 256
#define LC 512
#define HID 256
#define MD 283
#define DEPTH 7
#define LTOT (NCHUNK * LC)   // 131072 positions total

// Ping-pong activation buffers: (chunk, channel, pos) layout, fp32.
__device__ float g_bufA[NCHUNK * HID * LC];
__device__ float g_bufB[NCHUNK * HID * LC];
// Transposed tower weights: [layer][tap][ic][oc]
__device__ float g_wT[DEPTH * 3 * HID * HID];
// Transposed proj weights: [m][h]
__device__ float g_wpT[MD * HID];

// ---------------------------------------------------------------------------
// Weight prep: transpose tower_w (L,O,I,3) -> [L][t][i][o]; w_proj (H,M) -> [m][h]
// ---------------------------------------------------------------------------
__global__ void prep_kernel(const float* __restrict__ tower_w,
                            const float* __restrict__ w_proj) {
    int i = blockIdx.x * blockDim.x + threadIdx.x;
    if (i < DEPTH * 3 * HID * HID) {
        int oc = i & 255;
        int ic = (i >> 8) & 255;
        int lt = i >> 16;
        int t = lt % 3;
        int layer = lt / 3;
        g_wT[i] = tower_w[(((layer * HID + oc) * HID) + ic) * 3 + t];
    }
    if (i < MD * HID) {
        int h = i & 255;
        int m = i >> 8;
        g_wpT[i] = w_proj[h * MD + m];
    }
}

// ---------------------------------------------------------------------------
// Projection: out[n][h][l] = sum_m x[nl][m] * w_proj[h][m]
// GEMM M=131072 (pos), N=256 (h), K=283.  Tile 128x128, 256 threads, 8x8/thread.
// ---------------------------------------------------------------------------
__global__ __launch_bounds__(256, 2)
void proj_kernel(const float* __restrict__ x) {
    int m0 = blockIdx.x * 128;
    int hb = blockIdx.y * 128;
    __shared__ float As[128][16];
    __shared__ float Bs[16][128];
    int tid = threadIdx.x;
    int tx = tid & 15, ty = tid >> 4;
    float acc[8][8];
#pragma unroll
    for (int i = 0; i < 8; i++)
#pragma unroll
        for (int j = 0; j < 8; j++) acc[i][j] = 0.f;

    for (int kc = 0; kc < 288; kc += 16) {
        __syncthreads();
#pragma unroll
        for (int r = 0; r < 8; r++) {
            int e = r * 256 + tid;
            int p = e >> 4, k = e & 15;
            As[p][k] = (kc + k < MD) ? x[(size_t)(m0 + p) * MD + kc + k] : 0.f;
        }
#pragma unroll
        for (int r = 0; r < 8; r++) {
            int e = r * 256 + tid;
            int k = e >> 7, h = e & 127;
            Bs[k][h] = (kc + k < MD) ? g_wpT[(kc + k) * HID + hb + h] : 0.f;
        }
        __syncthreads();
#pragma unroll
        for (int k = 0; k < 16; k++) {
            float a[8], b[8];
#pragma unroll
            for (int i = 0; i < 8; i++) a[i] = As[ty * 8 + i][k];
            float4 b0 = *(const float4*)&Bs[k][tx * 8];
            float4 b1 = *(const float4*)&Bs[k][tx * 8 + 4];
            b[0] = b0.x; b[1] = b0.y; b[2] = b0.z; b[3] = b0.w;
            b[4] = b1.x; b[5] = b1.y; b[6] = b1.z; b[7] = b1.w;
#pragma unroll
            for (int i = 0; i < 8; i++)
#pragma unroll
                for (int j = 0; j < 8; j++) acc[i][j] = fmaf(a[i], b[j], acc[i][j]);
        }
    }
    // store: all 128 positions of this CTA lie in one chunk
    int n = m0 >> 9;
    int lbase = (m0 & 511) + ty * 8;
#pragma unroll
    for (int j = 0; j < 8; j++) {
        int oc = hb + tx * 8 + j;
        float* o = g_bufA + ((size_t)n * HID + oc) * LC + lbase;
        *(float4*)o = make_float4(acc[0][j], acc[1][j], acc[2][j], acc[3][j]);
        *(float4*)(o + 4) = make_float4(acc[4][j], acc[5][j], acc[6][j], acc[7][j]);
    }
}

// ---------------------------------------------------------------------------
// Dilated conv layer: out[n][oc][l] = gelu(c) + c,
//   c = b[oc] + sum_t sum_ic in[n][ic][l+(t-1)*d] * w[t][ic][oc]
// Implicit GEMM tile: 128 pos x 128 oc, K = 3*256 staged 3*16 at a time.
// ---------------------------------------------------------------------------
__global__ __launch_bounds__(256, 2)
void conv_kernel(int layer, int d, int srcB, const float* __restrict__ bias) {
    const float* in = srcB ? g_bufB : g_bufA;
    float* out = srcB ? g_bufA : g_bufB;
    int l0 = blockIdx.x * 128;
    int ocb = blockIdx.y * 128;
    int n = blockIdx.z;

    __shared__ float As[3 * 16 * 128];
    __shared__ float Bs[3 * 16 * 128];

    int tid = threadIdx.x;
    int tx = tid & 15, ty = tid >> 4;
    const float* inb = in + (size_t)n * HID * LC;
    const float* wL = g_wT + (size_t)layer * 3 * HID * HID;

    float acc[8][8];
#pragma unroll
    for (int i = 0; i < 8; i++)
#pragma unroll
        for (int j = 0; j < 8; j++) acc[i][j] = 0.f;

    for (int kc = 0; kc < HID; kc += 16) {
        __syncthreads();
#pragma unroll
        for (int r = 0; r < 24; r++) {
            int e = r * 256 + tid;
            int t = e >> 11;
            int k = (e >> 7) & 15;
            int p = e & 127;
            int pos = l0 + p + (t - 1) * d;
            float v = 0.f;
            if (pos >= 0 && pos < LC) v = inb[(kc + k) * LC + pos];
            As[e] = v;
            Bs[e] = wL[((t << 8) + kc + k) * HID + ocb + (e & 127)];
        }
        __syncthreads();
#pragma unroll
        for (int tk = 0; tk < 48; tk++) {
            float4 a0 = *(const float4*)&As[tk * 128 + ty * 8];
            float4 a1 = *(const float4*)&As[tk * 128 + ty * 8 + 4];
            float4 b0 = *(const float4*)&Bs[tk * 128 + tx * 8];
            float4 b1 = *(const float4*)&Bs[tk * 128 + tx * 8 + 4];
            float a[8], b[8];
            a[0] = a0.x; a[1] = a0.y; a[2] = a0.z; a[3] = a0.w;
            a[4] = a1.x; a[5] = a1.y; a[6] = a1.z; a[7] = a1.w;
            b[0] = b0.x; b[1] = b0.y; b[2] = b0.z; b[3] = b0.w;
            b[4] = b1.x; b[5] = b1.y; b[6] = b1.z; b[7] = b1.w;
#pragma unroll
            for (int i = 0; i < 8; i++)
#pragma unroll
                for (int j = 0; j < 8; j++) acc[i][j] = fmaf(a[i], b[j], acc[i][j]);
        }
    }

    int lb = l0 + ty * 8;
#pragma unroll
    for (int j = 0; j < 8; j++) {
        int oc = ocb + tx * 8 + j;
        float bs = bias[oc];
        float v[8];
#pragma unroll
        for (int i = 0; i < 8; i++) {
            float c = acc[i][j] + bs;
            float g = 0.5f * c * (1.f + erff(c * 0.70710678118654752f));
            v[i] = g + c;
        }
        float* o = out + ((size_t)n * HID + oc) * LC + lb;
        *(float4*)o = make_float4(v[0], v[1], v[2], v[3]);
        *(float4*)(o + 4) = make_float4(v[4], v[5], v[6], v[7]);
    }
}

// ---------------------------------------------------------------------------
// Heads: profile conv (K=20, pad 9/10) + mean-pool + atpm + mask.
// One CTA per chunk (256 CTAs x 256 threads). Final activations are in g_bufB.
// ---------------------------------------------------------------------------
__global__ __launch_bounds__(256)
void heads_kernel(const float* __restrict__ w_prof, const float* __restrict__ b_prof,
                  const float* __restrict__ w_atpm, const float* __restrict__ b_atpm,
                  const int* __restrict__ npq, float* __restrict__ out) {
    const float* in = g_bufB;
    int n = blockIdx.x;
    int tid = threadIdx.x;

    __shared__ float wp[HID * 20];
    __shared__ float wa[HID];
    __shared__ float row[LC];
    __shared__ float partial[256];

    for (int i = tid; i < HID * 20; i += 256) wp[i] = w_prof[i];
    wa[tid] = w_atpm[tid];

    float p0 = 0.f, p1 = 0.f, ap = 0.f;
    const float* base = in + (size_t)n * HID * LC;

    for (int ic = 0; ic < HID; ic++) {
        __syncthreads();
        row[tid] = base[ic * LC + tid];
        row[tid + 256] = base[ic * LC + tid + 256];
        __syncthreads();
        const float* wpr = &wp[ic * 20];
        float wv = wa[ic];
#pragma unroll
        for (int k = 0; k < 20; k++) {
            float w = wpr[k];
            int pos = tid + k - 9;
            if (pos >= 0 && pos < LC) p0 = fmaf(row[pos], w, p0);
            int pos2 = tid + 256 + k - 9;
            if (pos2 < LC) p1 = fmaf(row[pos2], w, p1);
        }
        ap = fmaf(wv, row[tid] + row[tid + 256], ap);
    }

    float bp = b_prof[0];
    out[256 + (size_t)n * LC + tid] = p0 + bp;
    out[256 + (size_t)n * LC + tid + 256] = p1 + bp;

    partial[tid] = ap;
    __syncthreads();
    for (int s = 128; s > 0; s >>= 1) {
        if (tid < s) partial[tid] += partial[tid + s];
        __syncthreads();
    }
    if (tid == 0) {
        float atpm = partial[0] * (1.f / 512.f) + b_atpm[0];
        int b = n >> 7, p = n & 127;
        // n_peaks dtype heuristic: JAX default x64-off -> int32; guard int64 too.
        int np;
        int q0 = npq[0], q1 = npq[1];
        if (q1 == 0) {
            int q2 = npq[2], q3 = npq[3];
            if (q3 == 0 && q2 >= 0 && q2 < 128 && q0 >= 0 && q0 < 128) {
                // looks like little-endian int64 [n0, n1]
                np = (b == 0) ? q0 : q2;
            } else {
                np = (b == 0) ? q0 : q1;
            }
        } else {
            np = (b == 0) ? q0 : q1;
        }
        out[n] = (p < np) ? atpm : 0.f;
    }
}

// ---------------------------------------------------------------------------
extern "C" void kernel_launch(void* const* d_in, const int* in_sizes, int n_in,
                              void* d_out, int out_size) {
    const float* x       = (const float*)d_in[0];
    const float* w_proj  = (const float*)d_in[1];
    const float* tower_w = (const float*)d_in[2];
    const float* tower_b = (const float*)d_in[3];
    const float* w_prof  = (const float*)d_in[4];
    const float* b_prof  = (const float*)d_in[5];
    const float* w_atpm  = (const float*)d_in[6];
    const float* b_atpm  = (const float*)d_in[7];
    const int*   n_peaks = (const int*)d_in[8];
    float* out = (float*)d_out;

    prep_kernel<<<(DEPTH * 3 * HID * HID + 255) / 256, 256>>>(tower_w, w_proj);
    proj_kernel<<<dim3(LTOT / 128, HID / 128), 256>>>(x);
    for (int i = 0; i < DEPTH; i++) {
        // layer i: dilation 2^(i+1); even i reads A writes B, odd i reads B writes A
        conv_kernel<<<dim3(LC / 128, HID / 128, NCHUNK), 256>>>(
            i, 2 << i, i & 1, tower_b + i * HID);
    }
    heads_kernel<<<NCHUNK, 256>>>(w_prof, b_prof, w_atpm, b_atpm, n_peaks, out);
}

// round 2
// speedup vs baseline: 1.0731x; 1.0731x over previous
#include <cuda_runtime.h>
#include <math.h>

#define NCHUNK 256
#define LC 512
#define HID 256
#define MD 283
#define DEPTH 7
#define LTOT (NCHUNK * LC)   // 131072 positions total

// Ping-pong activation buffers: (chunk, channel, pos) layout, fp32.
__device__ float g_bufA[NCHUNK * HID * LC];
__device__ float g_bufB[NCHUNK * HID * LC];
// Transposed tower weights: [layer][tap][ic][oc]
__device__ float g_wT[DEPTH * 3 * HID * HID];
// Transposed proj weights: [m][h]
__device__ float g_wpT[MD * HID];

// Packed f32x2 helpers (FFMA2 is PTX-only; ptxas never fuses from C++)
#define FMA2(d, a, b) asm("fma.rn.f32x2 %0, %1, %2, %3;" \
                          : "=l"(d) : "l"(a), "l"(b), "l"(d))
#define BCAST2(d, s) asm("mov.b64 %0, {%1, %1};" : "=l"(d) : "f"(s))
#define UNPACK2(lo, hi, v) asm("mov.b64 {%0, %1}, %2;" : "=f"(lo), "=f"(hi) : "l"(v))

// ---------------------------------------------------------------------------
// Weight prep: transpose tower_w (L,O,I,3) -> [L][t][i][o]; w_proj (H,M) -> [m][h]
// ---------------------------------------------------------------------------
__global__ void prep_kernel(const float* __restrict__ tower_w,
                            const float* __restrict__ w_proj) {
    int i = blockIdx.x * blockDim.x + threadIdx.x;
    if (i < DEPTH * 3 * HID * HID) {
        int oc = i & 255;
        int ic = (i >> 8) & 255;
        int lt = i >> 16;
        int t = lt % 3;
        int layer = lt / 3;
        g_wT[i] = tower_w[(((layer * HID + oc) * HID) + ic) * 3 + t];
    }
    if (i < MD * HID) {
        int h = i & 255;
        int m = i >> 8;
        g_wpT[i] = w_proj[h * MD + m];
    }
}

// ---------------------------------------------------------------------------
// Projection: out[n][h][l] = sum_m x[nl][m] * w_proj[h][m]
// GEMM M=131072 (pos), N=256 (h), K=283.  Tile 128x128, 256 threads, 8x8/thread.
// ---------------------------------------------------------------------------
__global__ __launch_bounds__(256, 2)
void proj_kernel(const float* __restrict__ x) {
    int m0 = blockIdx.x * 128;
    int hb = blockIdx.y * 128;
    __shared__ float As[128][16];
    __shared__ float Bs[16][128];
    int tid = threadIdx.x;
    int tx = tid & 15, ty = tid >> 4;
    float acc[8][8];
#pragma unroll
    for (int i = 0; i < 8; i++)
#pragma unroll
        for (int j = 0; j < 8; j++) acc[i][j] = 0.f;

    for (int kc = 0; kc < 288; kc += 16) {
        __syncthreads();
#pragma unroll
        for (int r = 0; r < 8; r++) {
            int e = r * 256 + tid;
            int p = e >> 4, k = e & 15;
            As[p][k] = (kc + k < MD) ? x[(size_t)(m0 + p) * MD + kc + k] : 0.f;
        }
#pragma unroll
        for (int r = 0; r < 8; r++) {
            int e = r * 256 + tid;
            int k = e >> 7, h = e & 127;
            Bs[k][h] = (kc + k < MD) ? g_wpT[(kc + k) * HID + hb + h] : 0.f;
        }
        __syncthreads();
#pragma unroll
        for (int k = 0; k < 16; k++) {
            float a[8], b[8];
#pragma unroll
            for (int i = 0; i < 8; i++) a[i] = As[ty * 8 + i][k];
            float4 b0 = *(const float4*)&Bs[k][tx * 8];
            float4 b1 = *(const float4*)&Bs[k][tx * 8 + 4];
            b[0] = b0.x; b[1] = b0.y; b[2] = b0.z; b[3] = b0.w;
            b[4] = b1.x; b[5] = b1.y; b[6] = b1.z; b[7] = b1.w;
#pragma unroll
            for (int i = 0; i < 8; i++)
#pragma unroll
                for (int j = 0; j < 8; j++) acc[i][j] = fmaf(a[i], b[j], acc[i][j]);
        }
    }
    // store: all 128 positions of this CTA lie in one chunk
    int n = m0 >> 9;
    int lbase = (m0 & 511) + ty * 8;
#pragma unroll
    for (int j = 0; j < 8; j++) {
        int oc = hb + tx * 8 + j;
        float* o = g_bufA + ((size_t)n * HID + oc) * LC + lbase;
        *(float4*)o = make_float4(acc[0][j], acc[1][j], acc[2][j], acc[3][j]);
        *(float4*)(o + 4) = make_float4(acc[4][j], acc[5][j], acc[6][j], acc[7][j]);
    }
}

// ---------------------------------------------------------------------------
// Dilated conv layer: out[n][oc][l] = gelu(c) + c,
//   c = b[oc] + sum_t sum_ic in[n][ic][l+(t-1)*d] * w[t][ic][oc]
// Implicit GEMM tile: 128 pos x 128 oc, K = 3*256 staged 3*16 at a time.
// Mainloop uses packed fma.rn.f32x2: accumulators paired along the position
// dim so A-pairs come directly from the 128-bit shared loads.
// ---------------------------------------------------------------------------
__global__ __launch_bounds__(256, 2)
void conv_kernel(int layer, int d, int srcB, const float* __restrict__ bias) {
    const float* in = srcB ? g_bufB : g_bufA;
    float* out = srcB ? g_bufA : g_bufB;
    int l0 = blockIdx.x * 128;
    int ocb = blockIdx.y * 128;
    int n = blockIdx.z;

    __shared__ float As[3 * 16 * 128];
    __shared__ float Bs[3 * 16 * 128];

    int tid = threadIdx.x;
    int tx = tid & 15, ty = tid >> 4;
    const float* inb = in + (size_t)n * HID * LC;
    const float* wL = g_wT + (size_t)layer * 3 * HID * HID;

    // acc[ip][j] = packed (pos 2ip, pos 2ip+1) for oc j
    unsigned long long acc[4][8];
#pragma unroll
    for (int i = 0; i < 4; i++)
#pragma unroll
        for (int j = 0; j < 8; j++) acc[i][j] = 0ull;

    for (int kc = 0; kc < HID; kc += 16) {
        __syncthreads();
#pragma unroll
        for (int r = 0; r < 24; r++) {
            int e = r * 256 + tid;
            int t = e >> 11;
            int k = (e >> 7) & 15;
            int p = e & 127;
            int pos = l0 + p + (t - 1) * d;
            float v = 0.f;
            if (pos >= 0 && pos < LC) v = inb[(kc + k) * LC + pos];
            As[e] = v;
            Bs[e] = wL[((t << 8) + kc + k) * HID + ocb + (e & 127)];
        }
        __syncthreads();
#pragma unroll
        for (int tk = 0; tk < 48; tk++) {
            int ao = tk * 128 + ty * 8;
            ulonglong2 A0 = *(const ulonglong2*)&As[ao];       // (a0,a1),(a2,a3)
            ulonglong2 A1 = *(const ulonglong2*)&As[ao + 4];   // (a4,a5),(a6,a7)
            unsigned long long ap[4];
            ap[0] = A0.x; ap[1] = A0.y; ap[2] = A1.x; ap[3] = A1.y;
            float4 b0 = *(const float4*)&Bs[tk * 128 + tx * 8];
            float4 b1 = *(const float4*)&Bs[tk * 128 + tx * 8 + 4];
            unsigned long long bb[8];
            BCAST2(bb[0], b0.x); BCAST2(bb[1], b0.y);
            BCAST2(bb[2], b0.z); BCAST2(bb[3], b0.w);
            BCAST2(bb[4], b1.x); BCAST2(bb[5], b1.y);
            BCAST2(bb[6], b1.z); BCAST2(bb[7], b1.w);
#pragma unroll
            for (int ip = 0; ip < 4; ip++)
#pragma unroll
                for (int j = 0; j < 8; j++) FMA2(acc[ip][j], ap[ip], bb[j]);
        }
    }

    int lb = l0 + ty * 8;
#pragma unroll
    for (int j = 0; j < 8; j++) {
        int oc = ocb + tx * 8 + j;
        float bs = bias[oc];
        float v[8];
#pragma unroll
        for (int ip = 0; ip < 4; ip++) {
            float lo, hi;
            UNPACK2(lo, hi, acc[ip][j]);
            float c0 = lo + bs;
            float c1 = hi + bs;
            v[2 * ip]     = 0.5f * c0 * (1.f + erff(c0 * 0.70710678118654752f)) + c0;
            v[2 * ip + 1] = 0.5f * c1 * (1.f + erff(c1 * 0.70710678118654752f)) + c1;
        }
        float* o = out + ((size_t)n * HID + oc) * LC + lb;
        *(float4*)o = make_float4(v[0], v[1], v[2], v[3]);
        *(float4*)(o + 4) = make_float4(v[4], v[5], v[6], v[7]);
    }
}

// ---------------------------------------------------------------------------
// Heads: profile conv (K=20, pad 9/10) + mean-pool + atpm + mask.
// One CTA per chunk (256 CTAs x 256 threads). Final activations are in g_bufB.
// ---------------------------------------------------------------------------
__global__ __launch_bounds__(256)
void heads_kernel(const float* __restrict__ w_prof, const float* __restrict__ b_prof,
                  const float* __restrict__ w_atpm, const float* __restrict__ b_atpm,
                  const int* __restrict__ npq, float* __restrict__ out) {
    const float* in = g_bufB;
    int n = blockIdx.x;
    int tid = threadIdx.x;

    __shared__ float wp[HID * 20];
    __shared__ float wa[HID];
    __shared__ float row[LC];
    __shared__ float partial[256];

    for (int i = tid; i < HID * 20; i += 256) wp[i] = w_prof[i];
    wa[tid] = w_atpm[tid];

    float p0 = 0.f, p1 = 0.f, ap = 0.f;
    const float* base = in + (size_t)n * HID * LC;

    for (int ic = 0; ic < HID; ic++) {
        __syncthreads();
        row[tid] = base[ic * LC + tid];
        row[tid + 256] = base[ic * LC + tid + 256];
        __syncthreads();
        const float* wpr = &wp[ic * 20];
        float wv = wa[ic];
#pragma unroll
        for (int k = 0; k < 20; k++) {
            float w = wpr[k];
            int pos = tid + k - 9;
            if (pos >= 0 && pos < LC) p0 = fmaf(row[pos], w, p0);
            int pos2 = tid + 256 + k - 9;
            if (pos2 < LC) p1 = fmaf(row[pos2], w, p1);
        }
        ap = fmaf(wv, row[tid] + row[tid + 256], ap);
    }

    float bp = b_prof[0];
    out[256 + (size_t)n * LC + tid] = p0 + bp;
    out[256 + (size_t)n * LC + tid + 256] = p1 + bp;

    partial[tid] = ap;
    __syncthreads();
    for (int s = 128; s > 0; s >>= 1) {
        if (tid < s) partial[tid] += partial[tid + s];
        __syncthreads();
    }
    if (tid == 0) {
        float atpm = partial[0] * (1.f / 512.f) + b_atpm[0];
        int b = n >> 7, p = n & 127;
        // n_peaks dtype heuristic: JAX default x64-off -> int32; guard int64 too.
        int np;
        int q0 = npq[0], q1 = npq[1];
        if (q1 == 0) {
            int q2 = npq[2], q3 = npq[3];
            if (q3 == 0 && q2 >= 0 && q2 < 128 && q0 >= 0 && q0 < 128) {
                // looks like little-endian int64 [n0, n1]
                np = (b == 0) ? q0 : q2;
            } else {
                np = (b == 0) ? q0 : q1;
            }
        } else {
            np = (b == 0) ? q0 : q1;
        }
        out[n] = (p < np) ? atpm : 0.f;
    }
}

// ---------------------------------------------------------------------------
extern "C" void kernel_launch(void* const* d_in, const int* in_sizes, int n_in,
                              void* d_out, int out_size) {
    const float* x       = (const float*)d_in[0];
    const float* w_proj  = (const float*)d_in[1];
    const float* tower_w = (const float*)d_in[2];
    const float* tower_b = (const float*)d_in[3];
    const float* w_prof  = (const float*)d_in[4];
    const float* b_prof  = (const float*)d_in[5];
    const float* w_atpm  = (const float*)d_in[6];
    const float* b_atpm  = (const float*)d_in[7];
    const int*   n_peaks = (const int*)d_in[8];
    float* out = (float*)d_out;

    prep_kernel<<<(DEPTH * 3 * HID * HID + 255) / 256, 256>>>(tower_w, w_proj);
    proj_kernel<<<dim3(LTOT / 128, HID / 128), 256>>>(x);
    for (int i = 0; i < DEPTH; i++) {
        // layer i: dilation 2^(i+1); even i reads A writes B, odd i reads B writes A
        conv_kernel<<<dim3(LC / 128, HID / 128, NCHUNK), 256>>>(
            i, 2 << i, i & 1, tower_b + i * HID);
    }
    heads_kernel<<<NCHUNK, 256>>>(w_prof, b_prof, w_atpm, b_atpm, n_peaks, out);
}

// round 3
// speedup vs baseline: 1.4129x; 1.3166x over previous
#include <cuda_runtime.h>
#include <math.h>

#define NCHUNK 256
#define LC 512
#define HID 256
#define MD 283
#define DEPTH 7
#define LTOT (NCHUNK * LC)   // 131072 positions total

// Ping-pong activation buffers: (chunk, channel, pos) layout, fp32.
__device__ float g_bufA[NCHUNK * HID * LC];
__device__ float g_bufB[NCHUNK * HID * LC];
// Tower weights pre-permuted into m16n8k8 tf32 B-fragment layout:
// [layer][kc16(16)][ohalf(2)][kstep(6)][ntile(16)][lane(32)][reg(2)]
__device__ unsigned g_wF[DEPTH * 16 * 2 * 6144];
// Transposed proj weights: [m][h]
__device__ float g_wpT[MD * HID];

// ---------------------------------------------------------------------------
// Weight prep:
//  - g_wF: tower_w (L,O,I,3) -> tf32 fragment layout (see above)
//  - g_wpT: w_proj (H,M) -> [m][h]
// ---------------------------------------------------------------------------
__global__ void prep_kernel(const float* __restrict__ tower_w,
                            const float* __restrict__ w_proj) {
    int i = blockIdx.x * blockDim.x + threadIdx.x;
    if (i < DEPTH * 16 * 2 * 6144) {
        int local = i % 6144;
        int blk = i / 6144;
        int reg = local & 1;
        int ln = (local >> 1) & 31;
        int nt = (local >> 6) & 15;
        int ks = local >> 10;             // 0..5
        int ohalf = blk & 1;
        int kc16 = (blk >> 1) & 15;
        int layer = blk >> 5;
        int t = ks >> 1;
        int ic = kc16 * 16 + (ln & 3) + 4 * reg + 8 * (ks & 1);
        int oc = ohalf * 128 + nt * 8 + (ln >> 2);
        float v = tower_w[(((layer * HID + oc) * HID) + ic) * 3 + t];
        unsigned tv; asm("cvt.rna.tf32.f32 %0, %1;" : "=r"(tv) : "f"(v));
        g_wF[i] = tv;
    }
    if (i < MD * HID) {
        int h = i & 255;
        int m = i >> 8;
        g_wpT[i] = w_proj[h * MD + m];
    }
}

// ---------------------------------------------------------------------------
// Projection: out[n][h][l] = sum_m x[nl][m] * w_proj[h][m]
// GEMM M=131072 (pos), N=256 (h), K=283.  Tile 128x128, fp32 SIMT 8x8/thread.
// ---------------------------------------------------------------------------
__global__ __launch_bounds__(256, 2)
void proj_kernel(const float* __restrict__ x) {
    int m0 = blockIdx.x * 128;
    int hb = blockIdx.y * 128;
    __shared__ float As[128][16];
    __shared__ float Bs[16][128];
    int tid = threadIdx.x;
    int tx = tid & 15, ty = tid >> 4;
    float acc[8][8];
#pragma unroll
    for (int i = 0; i < 8; i++)
#pragma unroll
        for (int j = 0; j < 8; j++) acc[i][j] = 0.f;

    for (int kc = 0; kc < 288; kc += 16) {
        __syncthreads();
#pragma unroll
        for (int r = 0; r < 8; r++) {
            int e = r * 256 + tid;
            int p = e >> 4, k = e & 15;
            As[p][k] = (kc + k < MD) ? x[(size_t)(m0 + p) * MD + kc + k] : 0.f;
        }
#pragma unroll
        for (int r = 0; r < 8; r++) {
            int e = r * 256 + tid;
            int k = e >> 7, h = e & 127;
            Bs[k][h] = (kc + k < MD) ? g_wpT[(kc + k) * HID + hb + h] : 0.f;
        }
        __syncthreads();
#pragma unroll
        for (int k = 0; k < 16; k++) {
            float a[8], b[8];
#pragma unroll
            for (int i = 0; i < 8; i++) a[i] = As[ty * 8 + i][k];
            float4 b0 = *(const float4*)&Bs[k][tx * 8];
            float4 b1 = *(const float4*)&Bs[k][tx * 8 + 4];
            b[0] = b0.x; b[1] = b0.y; b[2] = b0.z; b[3] = b0.w;
            b[4] = b1.x; b[5] = b1.y; b[6] = b1.z; b[7] = b1.w;
#pragma unroll
            for (int i = 0; i < 8; i++)
#pragma unroll
                for (int j = 0; j < 8; j++) acc[i][j] = fmaf(a[i], b[j], acc[i][j]);
        }
    }
    int n = m0 >> 9;
    int lbase = (m0 & 511) + ty * 8;
#pragma unroll
    for (int j = 0; j < 8; j++) {
        int oc = hb + tx * 8 + j;
        float* o = g_bufA + ((size_t)n * HID + oc) * LC + lbase;
        *(float4*)o = make_float4(acc[0][j], acc[1][j], acc[2][j], acc[3][j]);
        *(float4*)(o + 4) = make_float4(acc[4][j], acc[5][j], acc[6][j], acc[7][j]);
    }
}

// ---------------------------------------------------------------------------
// Dilated conv layer via tensor cores (mma.sync m16n8k8 tf32).
// CTA tile: 128 pos x 128 oc; 8 warps in 2(m) x 4(n); warp tile 64 pos x 32 oc.
// K = 3 taps x 256 ic, staged 3 x 16 ic per chunk = 6 k8-steps.
// A staged into exact A-fragment layout (one LDS.128 per fragment);
// B copied from pre-permuted g_wF (one float4 copy loop, conflict-free).
// ---------------------------------------------------------------------------
__global__ __launch_bounds__(256, 2)
void conv_kernel(int layer, int d, int srcB, const float* __restrict__ bias) {
    const float* in = srcB ? g_bufB : g_bufA;
    float* out = srcB ? g_bufA : g_bufB;
    int l0 = blockIdx.x * 128;
    int ocb = blockIdx.y * 128;
    int n = blockIdx.z;

    __shared__ unsigned As[6144];   // [kstep(6)][mtile(8)][lane(32)][reg(4)]
    __shared__ unsigned Bs[6144];   // [kstep(6)][ntile(16)][lane(32)][reg(2)]

    int tid = threadIdx.x;
    int lane = tid & 31;
    int warp = tid >> 5;
    int wm = warp & 1;
    int wn = warp >> 1;
    int tig = lane & 3;
    int grp = lane >> 2;

    const float* inb = in + (size_t)n * HID * LC;

    float acc[4][4][4];
#pragma unroll
    for (int i = 0; i < 4; i++)
#pragma unroll
        for (int j = 0; j < 4; j++)
#pragma unroll
            for (int c = 0; c < 4; c++) acc[i][j][c] = 0.f;

    for (int kc16 = 0; kc16 < 16; kc16++) {
        int kc = kc16 * 16;
        __syncthreads();
        // Stage A in fragment layout
#pragma unroll
        for (int r = 0; r < 24; r++) {
            int idx = r * 256 + tid;
            int reg = idx & 3;
            int ln = (idx >> 2) & 31;
            int mt = (idx >> 7) & 7;
            int ks = idx >> 10;
            int t = ks >> 1;
            int k = (ln & 3) + ((reg & 2) << 1) + ((ks & 1) << 3);
            int p = mt * 16 + (ln >> 2) + ((reg & 1) << 3);
            int pos = l0 + p + (t - 1) * d;
            float v = 0.f;
            if (pos >= 0 && pos < LC) v = inb[(kc + k) * LC + pos];
            unsigned tv; asm("cvt.rna.tf32.f32 %0, %1;" : "=r"(tv) : "f"(v));
            As[idx] = tv;
        }
        // Stage B: straight copy of pre-permuted fragment block
        const uint4* src = (const uint4*)(g_wF +
            (((size_t)layer * 16 + kc16) * 2 + blockIdx.y) * 6144);
#pragma unroll
        for (int r = 0; r < 6; r++)
            ((uint4*)Bs)[r * 256 + tid] = src[r * 256 + tid];
        __syncthreads();

#pragma unroll
        for (int ks = 0; ks < 6; ks++) {
            unsigned a[4][4], b[4][2];
#pragma unroll
            for (int i = 0; i < 4; i++) {
                uint4 av = ((const uint4*)As)[(ks * 8 + wm * 4 + i) * 32 + lane];
                a[i][0] = av.x; a[i][1] = av.y; a[i][2] = av.z; a[i][3] = av.w;
            }
#pragma unroll
            for (int j = 0; j < 4; j++) {
                uint2 bv = ((const uint2*)Bs)[(ks * 16 + wn * 4 + j) * 32 + lane];
                b[j][0] = bv.x; b[j][1] = bv.y;
            }
#pragma unroll
            for (int i = 0; i < 4; i++)
#pragma unroll
                for (int j = 0; j < 4; j++) {
                    asm volatile(
                        "mma.sync.aligned.m16n8k8.row.col.f32.tf32.tf32.f32 "
                        "{%0,%1,%2,%3}, {%4,%5,%6,%7}, {%8,%9}, {%0,%1,%2,%3};"
                        : "+f"(acc[i][j][0]), "+f"(acc[i][j][1]),
                          "+f"(acc[i][j][2]), "+f"(acc[i][j][3])
                        : "r"(a[i][0]), "r"(a[i][1]), "r"(a[i][2]), "r"(a[i][3]),
                          "r"(b[j][0]), "r"(b[j][1]));
                }
        }
    }

    // Epilogue: bias + gelu(c)+c, fragment-layout scatter (coalesces to 32B rows)
#pragma unroll
    for (int j = 0; j < 4; j++) {
        int oc0 = ocb + wn * 32 + j * 8 + tig * 2;
        float b0 = bias[oc0], b1 = bias[oc0 + 1];
#pragma unroll
        for (int i = 0; i < 4; i++) {
            int posb = l0 + wm * 64 + i * 16 + grp;
#pragma unroll
            for (int cr = 0; cr < 4; cr++) {
                int pos = posb + ((cr & 2) ? 8 : 0);
                int oc = oc0 + (cr & 1);
                float c = acc[i][j][cr] + ((cr & 1) ? b1 : b0);
                float g = 0.5f * c * (1.f + erff(c * 0.70710678118654752f)) + c;
                out[((size_t)n * HID + oc) * LC + pos] = g;
            }
        }
    }
}

// ---------------------------------------------------------------------------
// Heads: profile conv (K=20, pad 9/10) + mean-pool + atpm + mask.
// ---------------------------------------------------------------------------
__global__ __launch_bounds__(256)
void heads_kernel(const float* __restrict__ w_prof, const float* __restrict__ b_prof,
                  const float* __restrict__ w_atpm, const float* __restrict__ b_atpm,
                  const int* __restrict__ npq, float* __restrict__ out) {
    const float* in = g_bufB;
    int n = blockIdx.x;
    int tid = threadIdx.x;

    __shared__ float wp[HID * 20];
    __shared__ float wa[HID];
    __shared__ float row[LC];
    __shared__ float partial[256];

    for (int i = tid; i < HID * 20; i += 256) wp[i] = w_prof[i];
    wa[tid] = w_atpm[tid];

    float p0 = 0.f, p1 = 0.f, ap = 0.f;
    const float* base = in + (size_t)n * HID * LC;

    for (int ic = 0; ic < HID; ic++) {
        __syncthreads();
        row[tid] = base[ic * LC + tid];
        row[tid + 256] = base[ic * LC + tid + 256];
        __syncthreads();
        const float* wpr = &wp[ic * 20];
        float wv = wa[ic];
#pragma unroll
        for (int k = 0; k < 20; k++) {
            float w = wpr[k];
            int pos = tid + k - 9;
            if (pos >= 0 && pos < LC) p0 = fmaf(row[pos], w, p0);
            int pos2 = tid + 256 + k - 9;
            if (pos2 < LC) p1 = fmaf(row[pos2], w, p1);
        }
        ap = fmaf(wv, row[tid] + row[tid + 256], ap);
    }

    float bp = b_prof[0];
    out[256 + (size_t)n * LC + tid] = p0 + bp;
    out[256 + (size_t)n * LC + tid + 256] = p1 + bp;

    partial[tid] = ap;
    __syncthreads();
    for (int s = 128; s > 0; s >>= 1) {
        if (tid < s) partial[tid] += partial[tid + s];
        __syncthreads();
    }
    if (tid == 0) {
        float atpm = partial[0] * (1.f / 512.f) + b_atpm[0];
        int b = n >> 7, p = n & 127;
        int np;
        int q0 = npq[0], q1 = npq[1];
        if (q1 == 0) {
            int q2 = npq[2], q3 = npq[3];
            if (q3 == 0 && q2 >= 0 && q2 < 128 && q0 >= 0 && q0 < 128) {
                np = (b == 0) ? q0 : q2;   // little-endian int64 [n0, n1]
            } else {
                np = (b == 0) ? q0 : q1;
            }
        } else {
            np = (b == 0) ? q0 : q1;
        }
        out[n] = (p < np) ? atpm : 0.f;
    }
}

// ---------------------------------------------------------------------------
extern "C" void kernel_launch(void* const* d_in, const int* in_sizes, int n_in,
                              void* d_out, int out_size) {
    const float* x       = (const float*)d_in[0];
    const float* w_proj  = (const float*)d_in[1];
    const float* tower_w = (const float*)d_in[2];
    const float* tower_b = (const float*)d_in[3];
    const float* w_prof  = (const float*)d_in[4];
    const float* b_prof  = (const float*)d_in[5];
    const float* w_atpm  = (const float*)d_in[6];
    const float* b_atpm  = (const float*)d_in[7];
    const int*   n_peaks = (const int*)d_in[8];
    float* out = (float*)d_out;

    prep_kernel<<<(DEPTH * 16 * 2 * 6144 + 255) / 256, 256>>>(tower_w, w_proj);
    proj_kernel<<<dim3(LTOT / 128, HID / 128), 256>>>(x);
    for (int i = 0; i < DEPTH; i++) {
        conv_kernel<<<dim3(LC / 128, HID / 128, NCHUNK), 256>>>(
            i, 2 << i, i & 1, tower_b + i * HID);
    }
    heads_kernel<<<NCHUNK, 256>>>(w_prof, b_prof, w_atpm, b_atpm, n_peaks, out);
}

// round 4
// speedup vs baseline: 2.6577x; 1.8810x over previous
#include <cuda_runtime.h>
#include <math.h>

#define NCHUNK 256
#define LC 512
#define HID 256
#define MD 283
#define DEPTH 7
#define LTOT (NCHUNK * LC)   // 131072 positions total

#define PITCH 136            // floats per A-row; 136 % 32 == 8 -> conflict-free frags
#define ASMEM (48 * PITCH)   // 6528 words
#define BSMEM 6144
#define CONV_SMEM_BYTES ((ASMEM + BSMEM) * 4)

// Ping-pong activation buffers: (chunk, channel, pos) layout, fp32.
__device__ float g_bufA[NCHUNK * HID * LC];
__device__ float g_bufB[NCHUNK * HID * LC];
// Tower weights pre-permuted into m16n8k8 tf32 B-fragment layout:
// [layer][kc16(16)][ohalf(2)][kstep(6)][ntile(16)][lane(32)][reg(2)]
__device__ unsigned g_wF[DEPTH * 16 * 2 * 6144];
// Transposed proj weights: [m][h]
__device__ float g_wpT[MD * HID];

// ---------------------------------------------------------------------------
// Weight prep
// ---------------------------------------------------------------------------
__global__ void prep_kernel(const float* __restrict__ tower_w,
                            const float* __restrict__ w_proj) {
    int i = blockIdx.x * blockDim.x + threadIdx.x;
    if (i < DEPTH * 16 * 2 * 6144) {
        int local = i % 6144;
        int blk = i / 6144;
        int reg = local & 1;
        int ln = (local >> 1) & 31;
        int nt = (local >> 6) & 15;
        int ks = local >> 10;             // 0..5
        int ohalf = blk & 1;
        int kc16 = (blk >> 1) & 15;
        int layer = blk >> 5;
        int t = ks >> 1;
        int ic = kc16 * 16 + (ln & 3) + 4 * reg + 8 * (ks & 1);
        int oc = ohalf * 128 + nt * 8 + (ln >> 2);
        float v = tower_w[(((layer * HID + oc) * HID) + ic) * 3 + t];
        unsigned tv; asm("cvt.rna.tf32.f32 %0, %1;" : "=r"(tv) : "f"(v));
        g_wF[i] = tv;
    }
    if (i < MD * HID) {
        int h = i & 255;
        int m = i >> 8;
        g_wpT[i] = w_proj[h * MD + m];
    }
}

// ---------------------------------------------------------------------------
// Projection: GEMM M=131072 (pos), N=256 (h), K=283. fp32 SIMT 8x8/thread.
// ---------------------------------------------------------------------------
__global__ __launch_bounds__(256, 2)
void proj_kernel(const float* __restrict__ x) {
    int m0 = blockIdx.x * 128;
    int hb = blockIdx.y * 128;
    __shared__ float As[128][16];
    __shared__ float Bs[16][128];
    int tid = threadIdx.x;
    int tx = tid & 15, ty = tid >> 4;
    float acc[8][8];
#pragma unroll
    for (int i = 0; i < 8; i++)
#pragma unroll
        for (int j = 0; j < 8; j++) acc[i][j] = 0.f;

    for (int kc = 0; kc < 288; kc += 16) {
        __syncthreads();
#pragma unroll
        for (int r = 0; r < 8; r++) {
            int e = r * 256 + tid;
            int p = e >> 4, k = e & 15;
            As[p][k] = (kc + k < MD) ? x[(size_t)(m0 + p) * MD + kc + k] : 0.f;
        }
#pragma unroll
        for (int r = 0; r < 8; r++) {
            int e = r * 256 + tid;
            int k = e >> 7, h = e & 127;
            Bs[k][h] = (kc + k < MD) ? g_wpT[(kc + k) * HID + hb + h] : 0.f;
        }
        __syncthreads();
#pragma unroll
        for (int k = 0; k < 16; k++) {
            float a[8], b[8];
#pragma unroll
            for (int i = 0; i < 8; i++) a[i] = As[ty * 8 + i][k];
            float4 b0 = *(const float4*)&Bs[k][tx * 8];
            float4 b1 = *(const float4*)&Bs[k][tx * 8 + 4];
            b[0] = b0.x; b[1] = b0.y; b[2] = b0.z; b[3] = b0.w;
            b[4] = b1.x; b[5] = b1.y; b[6] = b1.z; b[7] = b1.w;
#pragma unroll
            for (int i = 0; i < 8; i++)
#pragma unroll
                for (int j = 0; j < 8; j++) acc[i][j] = fmaf(a[i], b[j], acc[i][j]);
        }
    }
    int n = m0 >> 9;
    int lbase = (m0 & 511) + ty * 8;
#pragma unroll
    for (int j = 0; j < 8; j++) {
        int oc = hb + tx * 8 + j;
        float* o = g_bufA + ((size_t)n * HID + oc) * LC + lbase;
        *(float4*)o = make_float4(acc[0][j], acc[1][j], acc[2][j], acc[3][j]);
        *(float4*)(o + 4) = make_float4(acc[4][j], acc[5][j], acc[6][j], acc[7][j]);
    }
}

// ---------------------------------------------------------------------------
// Dilated conv layer via mma.sync m16n8k8 tf32.
// CTA tile 128 pos x 128 oc; 8 warps 2(m) x 4(n); warp tile 64 pos x 32 oc.
// A staged in NATURAL [row=(t,ic)][pos] layout (coalesced float2 LDG + STS.64),
// fragments gathered in mainloop via conflict-free LDS.32 (pitch 136).
// B copied from pre-permuted g_wF fragment layout (coalesced uint4).
// ---------------------------------------------------------------------------
__global__ __launch_bounds__(256, 2)
void conv_kernel(int layer, int d, int srcB, const float* __restrict__ bias) {
    extern __shared__ unsigned sm[];
    unsigned* smA = sm;            // ASMEM words
    unsigned* smB = sm + ASMEM;    // BSMEM words

    const float* in = srcB ? g_bufB : g_bufA;
    float* out = srcB ? g_bufA : g_bufB;
    int l0 = blockIdx.x * 128;
    int ocb = blockIdx.y * 128;
    int n = blockIdx.z;

    int tid = threadIdx.x;
    int lane = tid & 31;
    int warp = tid >> 5;
    int wm = warp & 1;
    int wn = warp >> 1;
    int tig = lane & 3;
    int grp = lane >> 2;

    const float* inb = in + (size_t)n * HID * LC;

    float acc[4][4][4];
#pragma unroll
    for (int i = 0; i < 4; i++)
#pragma unroll
        for (int j = 0; j < 4; j++)
#pragma unroll
            for (int c = 0; c < 4; c++) acc[i][j][c] = 0.f;

    for (int kc16 = 0; kc16 < 16; kc16++) {
        int kc = kc16 * 16;
        __syncthreads();
        // Stage A: 48 rows x 128 pos, coalesced float2 loads, tf32 convert
#pragma unroll
        for (int r = 0; r < 12; r++) {
            int e = r * 256 + tid;          // 0..3071
            int row = e >> 6;               // 0..47 : t*16 + kk
            int p = (e & 63) << 1;          // 0..126 even
            int t = row >> 4;
            int pos = l0 + p + (t - 1) * d; // even (d even, l0 mult 128)
            float2 v = make_float2(0.f, 0.f);
            if ((unsigned)pos < LC)
                v = *(const float2*)(inb + (size_t)(kc + (row & 15)) * LC + pos);
            unsigned u0, u1;
            asm("cvt.rna.tf32.f32 %0, %1;" : "=r"(u0) : "f"(v.x));
            asm("cvt.rna.tf32.f32 %0, %1;" : "=r"(u1) : "f"(v.y));
            *(uint2*)(smA + row * PITCH + p) = make_uint2(u0, u1);
        }
        // Stage B: straight copy of pre-permuted fragment block
        const uint4* src = (const uint4*)(g_wF +
            (((size_t)layer * 16 + kc16) * 2 + blockIdx.y) * 6144);
#pragma unroll
        for (int r = 0; r < 6; r++)
            ((uint4*)smB)[r * 256 + tid] = src[r * 256 + tid];
        __syncthreads();

#pragma unroll
        for (int ks = 0; ks < 6; ks++) {
            int rb = (ks >> 1) * 16 + (ks & 1) * 8;
            const unsigned* ar0 = smA + (rb + tig) * PITCH + grp + wm * 64;
            const unsigned* ar1 = smA + (rb + tig + 4) * PITCH + grp + wm * 64;
            unsigned a[4][4], b[4][2];
#pragma unroll
            for (int i = 0; i < 4; i++) {
                a[i][0] = ar0[i * 16];
                a[i][1] = ar0[i * 16 + 8];
                a[i][2] = ar1[i * 16];
                a[i][3] = ar1[i * 16 + 8];
            }
#pragma unroll
            for (int j = 0; j < 4; j++) {
                uint2 bv = ((const uint2*)smB)[(ks * 16 + wn * 4 + j) * 32 + lane];
                b[j][0] = bv.x; b[j][1] = bv.y;
            }
#pragma unroll
            for (int i = 0; i < 4; i++)
#pragma unroll
                for (int j = 0; j < 4; j++) {
                    asm volatile(
                        "mma.sync.aligned.m16n8k8.row.col.f32.tf32.tf32.f32 "
                        "{%0,%1,%2,%3}, {%4,%5,%6,%7}, {%8,%9}, {%0,%1,%2,%3};"
                        : "+f"(acc[i][j][0]), "+f"(acc[i][j][1]),
                          "+f"(acc[i][j][2]), "+f"(acc[i][j][3])
                        : "r"(a[i][0]), "r"(a[i][1]), "r"(a[i][2]), "r"(a[i][3]),
                          "r"(b[j][0]), "r"(b[j][1]));
                }
        }
    }

    // Epilogue: bias + gelu(c)+c
#pragma unroll
    for (int j = 0; j < 4; j++) {
        int oc0 = ocb + wn * 32 + j * 8 + tig * 2;
        float b0 = bias[oc0], b1 = bias[oc0 + 1];
#pragma unroll
        for (int i = 0; i < 4; i++) {
            int posb = l0 + wm * 64 + i * 16 + grp;
#pragma unroll
            for (int cr = 0; cr < 4; cr++) {
                int pos = posb + ((cr & 2) ? 8 : 0);
                int oc = oc0 + (cr & 1);
                float c = acc[i][j][cr] + ((cr & 1) ? b1 : b0);
                float g = 0.5f * c * (1.f + erff(c * 0.70710678118654752f)) + c;
                out[((size_t)n * HID + oc) * LC + pos] = g;
            }
        }
    }
}

// ---------------------------------------------------------------------------
// Heads: profile conv (K=20, pad 9/10) + mean-pool + atpm + mask.
// ---------------------------------------------------------------------------
__global__ __launch_bounds__(256)
void heads_kernel(const float* __restrict__ w_prof, const float* __restrict__ b_prof,
                  const float* __restrict__ w_atpm, const float* __restrict__ b_atpm,
                  const int* __restrict__ npq, float* __restrict__ out) {
    const float* in = g_bufB;
    int n = blockIdx.x;
    int tid = threadIdx.x;

    __shared__ float wp[HID * 20];
    __shared__ float wa[HID];
    __shared__ float row[LC];
    __shared__ float partial[256];

    for (int i = tid; i < HID * 20; i += 256) wp[i] = w_prof[i];
    wa[tid] = w_atpm[tid];

    float p0 = 0.f, p1 = 0.f, ap = 0.f;
    const float* base = in + (size_t)n * HID * LC;

    for (int ic = 0; ic < HID; ic++) {
        __syncthreads();
        row[tid] = base[ic * LC + tid];
        row[tid + 256] = base[ic * LC + tid + 256];
        __syncthreads();
        const float* wpr = &wp[ic * 20];
        float wv = wa[ic];
#pragma unroll
        for (int k = 0; k < 20; k++) {
            float w = wpr[k];
            int pos = tid + k - 9;
            if (pos >= 0 && pos < LC) p0 = fmaf(row[pos], w, p0);
            int pos2 = tid + 256 + k - 9;
            if (pos2 < LC) p1 = fmaf(row[pos2], w, p1);
        }
        ap = fmaf(wv, row[tid] + row[tid + 256], ap);
    }

    float bp = b_prof[0];
    out[256 + (size_t)n * LC + tid] = p0 + bp;
    out[256 + (size_t)n * LC + tid + 256] = p1 + bp;

    partial[tid] = ap;
    __syncthreads();
    for (int s = 128; s > 0; s >>= 1) {
        if (tid < s) partial[tid] += partial[tid + s];
        __syncthreads();
    }
    if (tid == 0) {
        float atpm = partial[0] * (1.f / 512.f) + b_atpm[0];
        int b = n >> 7, p = n & 127;
        int np;
        int q0 = npq[0], q1 = npq[1];
        if (q1 == 0) {
            int q2 = npq[2], q3 = npq[3];
            if (q3 == 0 && q2 >= 0 && q2 < 128 && q0 >= 0 && q0 < 128) {
                np = (b == 0) ? q0 : q2;   // little-endian int64 [n0, n1]
            } else {
                np = (b == 0) ? q0 : q1;
            }
        } else {
            np = (b == 0) ? q0 : q1;
        }
        out[n] = (p < np) ? atpm : 0.f;
    }
}

// ---------------------------------------------------------------------------
extern "C" void kernel_launch(void* const* d_in, const int* in_sizes, int n_in,
                              void* d_out, int out_size) {
    const float* x       = (const float*)d_in[0];
    const float* w_proj  = (const float*)d_in[1];
    const float* tower_w = (const float*)d_in[2];
    const float* tower_b = (const float*)d_in[3];
    const float* w_prof  = (const float*)d_in[4];
    const float* b_prof  = (const float*)d_in[5];
    const float* w_atpm  = (const float*)d_in[6];
    const float* b_atpm  = (const float*)d_in[7];
    const int*   n_peaks = (const int*)d_in[8];
    float* out = (float*)d_out;

    cudaFuncSetAttribute(conv_kernel,
                         cudaFuncAttributeMaxDynamicSharedMemorySize,
                         CONV_SMEM_BYTES);

    prep_kernel<<<(DEPTH * 16 * 2 * 6144 + 255) / 256, 256>>>(tower_w, w_proj);
    proj_kernel<<<dim3(LTOT / 128, HID / 128), 256>>>(x);
    for (int i = 0; i < DEPTH; i++) {
        conv_kernel<<<dim3(LC / 128, HID / 128, NCHUNK), 256, CONV_SMEM_BYTES>>>(
            i, 2 << i, i & 1, tower_b + i * HID);
    }
    heads_kernel<<<NCHUNK, 256>>>(w_prof, b_prof, w_atpm, b_atpm, n_peaks, out);
}